// round 5
// baseline (speedup 1.0000x reference)
#include <cuda_runtime.h>
#include <cuda_bf16.h>
#include <stdint.h>

#define NN 200000
#define NE 400000
#define DV 133
#define DE 14
#define DH 200

// ---------------------------------------------------------------------------
// Scratch
// ---------------------------------------------------------------------------
__device__ float g_VW[(size_t)NN * DH];
__device__ float g_H0[(size_t)NE * DH];
__device__ float g_H1[(size_t)NE * DH];
__device__ float g_Q [(size_t)NE * DH];
__device__ float g_NM[(size_t)NN * DH];
__device__ float g_MV[(size_t)NN * DH];
__device__ __nv_bfloat16 g_BThi[192000];
__device__ __nv_bfloat16 g_BTlo[192000];
__device__ int g_idx64;

#define BT_WV   0LL       /* K=133 Kpad=192 */
#define BT_WE   38400LL   /* K=14  Kpad=64  */
#define BT_WH   51200LL   /* K=200 Kpad=256 */
#define BT_WOV  102400LL  /* K=133 Kpad=192 */
#define BT_WOH  140800LL  /* K=200 Kpad=256 */

// ---------------------------------------------------------------------------
__global__ void k_detect(const unsigned int* __restrict__ ei) {
    if (threadIdx.x == 0 && blockIdx.x == 0) {
        int all0 = 1;
        for (int i = 1; i < 256; i += 2)
            if (ei[i] != 0u) { all0 = 0; break; }
        g_idx64 = all0;
    }
}
__device__ __forceinline__ int load_idx(const void* p, long long i, int is64) {
    if (is64) return (int)((const long long*)p)[i];
    return ((const int*)p)[i];
}

// Bt[n][k] = W[roff+k][n], split hi/lo bf16, K-padded with zeros
__global__ void k_makeB(const float* __restrict__ W, int roff, int K, int Kpad, long long off) {
    long long tot = 200LL * Kpad;
    for (long long i = (long long)blockIdx.x * blockDim.x + threadIdx.x; i < tot;
         i += (long long)gridDim.x * blockDim.x) {
        int n = (int)(i / Kpad), k = (int)(i % Kpad);
        float v = (k < K) ? W[(size_t)(roff + k) * DH + n] : 0.f;
        __nv_bfloat16 h = __float2bfloat16(v);
        g_BThi[off + i] = h;
        g_BTlo[off + i] = __float2bfloat16(v - __bfloat162float(h));
    }
}

__global__ void k_zero(float4* __restrict__ p, long long n4) {
    float4 z = make_float4(0.f, 0.f, 0.f, 0.f);
    for (long long i = (long long)blockIdx.x * blockDim.x + threadIdx.x; i < n4;
         i += (long long)gridDim.x * blockDim.x)
        p[i] = z;
}

// ---------------------------------------------------------------------------
// mma.sync m16n8k16 bf16 (base ISA, runs on tensor pipe)
// ---------------------------------------------------------------------------
__device__ __forceinline__ void mma16816(float* c, const uint32_t* a, const uint32_t* b) {
    asm volatile("mma.sync.aligned.m16n8k16.row.col.f32.bf16.bf16.f32 "
        "{%0,%1,%2,%3}, {%4,%5,%6,%7}, {%8,%9}, {%0,%1,%2,%3};"
        : "+f"(c[0]), "+f"(c[1]), "+f"(c[2]), "+f"(c[3])
        : "r"(a[0]), "r"(a[1]), "r"(a[2]), "r"(a[3]), "r"(b[0]), "r"(b[1]));
}

__device__ __forceinline__ void split2(float v0, float v1, uint32_t& hw, uint32_t& lw) {
    __nv_bfloat16 h0 = __float2bfloat16(v0);
    __nv_bfloat16 h1 = __float2bfloat16(v1);
    __nv_bfloat16 l0 = __float2bfloat16(v0 - __bfloat162float(h0));
    __nv_bfloat16 l1 = __float2bfloat16(v1 - __bfloat162float(h1));
    hw = (uint32_t)__bfloat16_as_ushort(h0) | ((uint32_t)__bfloat16_as_ushort(h1) << 16);
    lw = (uint32_t)__bfloat16_as_ushort(l0) | ((uint32_t)__bfloat16_as_ushort(l1) << 16);
}

#define PITCH 40               /* words per smem row: conflict-free LDS.64 */
#define SW_AH 0
#define SW_AL 5120             /* 128*40 */
#define SW_BH 10240
#define SW_BL 18240            /* +200*40 */
#define SW_WORDS 26240         /* *4 = 104960 bytes */

// ---------------------------------------------------------------------------
// C[Mrows,200] = A[Mrows,K] @ W[K,200]  (3-term split bf16 mma, fp32 acc)
// mode 0: C = acc
// mode 1: C = relu(acc + addend[idx[row]] + bias)
// mode 2: C = acc; scat[idx[row]] += acc (atomic)
// mode 3: C = relu(acc + addend[row] + bias)
// ---------------------------------------------------------------------------
__global__ __launch_bounds__(256, 1)
void k_gemm(const float* __restrict__ A, int Mrows, int K, int Kpad,
            long long bt_off, int mode,
            const float* __restrict__ bias,
            const float* __restrict__ addend,
            const void* __restrict__ idx, long long idx_off,
            float* __restrict__ C, float* __restrict__ scat)
{
    extern __shared__ uint32_t sw[];
    const int tid = threadIdx.x, wid = tid >> 5, lane = tid & 31;
    const int g = lane >> 2, tig = lane & 3;
    const int e0 = blockIdx.x * 128, m0 = wid * 16;
    const int KSTEPS = (K + 15) >> 4;
    const int CC = (KSTEPS + 3) >> 2;
    const int kpw = Kpad >> 1;
    const uint32_t* __restrict__ Bh = (const uint32_t*)g_BThi + (bt_off >> 1);
    const uint32_t* __restrict__ Bl = (const uint32_t*)g_BTlo + (bt_off >> 1);

    float acc[25][4];
#pragma unroll
    for (int nf = 0; nf < 25; nf++)
#pragma unroll
        for (int i = 0; i < 4; i++) acc[nf][i] = 0.f;

    for (int c = 0; c < CC; c++) {
        const int kb = c << 6;
        __syncthreads();
        // A tile: 128 rows x 32 words, permuted [0,4,1,5,2,6,3,7] per kstep
        for (int pos = tid; pos < 4096; pos += 256) {
            int row = pos >> 5, q = pos & 31;
            int ql = q & 7, s = q >> 3;
            int ow = (ql & 1) ? ((ql >> 1) + 4) : (ql >> 1);
            int k0 = kb + ((s << 3) + ow) * 2;
            int r = e0 + row;
            float v0 = 0.f, v1 = 0.f;
            if (r < Mrows) {
                const float* ap = A + (size_t)r * K;
                if (k0 < K) v0 = ap[k0];
                if (k0 + 1 < K) v1 = ap[k0 + 1];
            }
            uint32_t hw, lw;
            split2(v0, v1, hw, lw);
            sw[SW_AH + row * PITCH + q] = hw;
            sw[SW_AL + row * PITCH + q] = lw;
        }
        // B tile: 200 rows x 32 words (pre-split, just permute-copy)
        for (int pos = tid; pos < 6400; pos += 256) {
            int n = pos >> 5, q = pos & 31;
            int ql = q & 7, s = q >> 3;
            int ow = (ql & 1) ? ((ql >> 1) + 4) : (ql >> 1);
            int wi = n * kpw + (kb >> 1) + (s << 3) + ow;
            sw[SW_BH + n * PITCH + q] = Bh[wi];
            sw[SW_BL + n * PITCH + q] = Bl[wi];
        }
        __syncthreads();

        int ksl = KSTEPS - (c << 2);
        if (ksl > 4) ksl = 4;
        for (int s = 0; s < ksl; s++) {
            uint32_t ah[4], al[4];
            int aw = (m0 + g) * PITCH + (s << 3) + (tig << 1);
            {
                uint2 t0 = *(const uint2*)&sw[SW_AH + aw];
                uint2 t1 = *(const uint2*)&sw[SW_AH + aw + 8 * PITCH];
                ah[0] = t0.x; ah[2] = t0.y; ah[1] = t1.x; ah[3] = t1.y;
                uint2 u0 = *(const uint2*)&sw[SW_AL + aw];
                uint2 u1 = *(const uint2*)&sw[SW_AL + aw + 8 * PITCH];
                al[0] = u0.x; al[2] = u0.y; al[1] = u1.x; al[3] = u1.y;
            }
#pragma unroll
            for (int nf = 0; nf < 25; nf++) {
                int bw = (nf * 8 + g) * PITCH + (s << 3) + (tig << 1);
                uint2 bh2 = *(const uint2*)&sw[SW_BH + bw];
                uint2 bl2 = *(const uint2*)&sw[SW_BL + bw];
                uint32_t bh[2] = { bh2.x, bh2.y };
                uint32_t bl[2] = { bl2.x, bl2.y };
                mma16816(acc[nf], ah, bh);
                mma16816(acc[nf], al, bh);
                mma16816(acc[nf], ah, bl);
            }
        }
    }

    // ---- epilogue ----
    const int is64 = g_idx64;
    const int r1 = e0 + m0 + g, r2 = r1 + 8;
    const bool v1 = r1 < Mrows, v2 = r2 < Mrows;
    long long gi1 = 0, gi2 = 0;
    if (mode == 1 || mode == 2) {
        if (v1) gi1 = load_idx(idx, idx_off + r1, is64);
        if (v2) gi2 = load_idx(idx, idx_off + r2, is64);
    }
    const float* ar1 = (mode == 1) ? addend + (size_t)gi1 * DH
                     : (mode == 3) ? addend + (size_t)r1 * DH : nullptr;
    const float* ar2 = (mode == 1) ? addend + (size_t)gi2 * DH
                     : (mode == 3) ? addend + (size_t)r2 * DH : nullptr;

#pragma unroll
    for (int nf = 0; nf < 25; nf++) {
        int col = nf * 8 + tig * 2;
        if (v1) {
            float x0 = acc[nf][0], x1 = acc[nf][1];
            if (mode == 1 || mode == 3) {
                x0 = fmaxf(x0 + ar1[col] + bias[col], 0.f);
                x1 = fmaxf(x1 + ar1[col + 1] + bias[col + 1], 0.f);
            }
            *(float2*)&C[(size_t)r1 * DH + col] = make_float2(x0, x1);
            if (mode == 2) {
                atomicAdd(&scat[(size_t)gi1 * DH + col], x0);
                atomicAdd(&scat[(size_t)gi1 * DH + col + 1], x1);
            }
        }
        if (v2) {
            float x2 = acc[nf][2], x3 = acc[nf][3];
            if (mode == 1 || mode == 3) {
                x2 = fmaxf(x2 + ar2[col] + bias[col], 0.f);
                x3 = fmaxf(x3 + ar2[col + 1] + bias[col + 1], 0.f);
            }
            *(float2*)&C[(size_t)r2 * DH + col] = make_float2(x2, x3);
            if (mode == 2) {
                atomicAdd(&scat[(size_t)gi2 * DH + col], x2);
                atomicAdd(&scat[(size_t)gi2 * DH + col + 1], x3);
            }
        }
    }
}

// ---------------------------------------------------------------------------
// H = relu(H0 + NMQ[src] - Q[rev]*(rev!=e) + bh); store Hout or scatter MV[src]
// ---------------------------------------------------------------------------
__global__ __launch_bounds__(200) void k_combine(
    const float* __restrict__ Q, const float* __restrict__ H0b,
    const float* __restrict__ NMQ, const float* __restrict__ bh,
    const void* __restrict__ EI, const void* __restrict__ REV,
    float* __restrict__ Hout, float* __restrict__ MV)
{
    __shared__ int s_src[32], s_rev[32];
    const int tid = threadIdx.x;
    const long long e0 = (long long)blockIdx.x * 32;
    const int is64 = g_idx64;
    if (tid < 32) {
        s_src[tid] = load_idx(EI, e0 + tid, is64);
        long long r = (long long)load_idx(REV, e0 + tid, is64);
        s_rev[tid] = (r == e0 + tid) ? -1 : (int)r;
    }
    __syncthreads();
    const float b = bh[tid];
#pragma unroll 4
    for (int e = 0; e < 32; e++) {
        long long ee = e0 + e;
        int s = s_src[e], r = s_rev[e];
        float m = H0b[(size_t)ee * DH + tid] + NMQ[(size_t)s * DH + tid] + b;
        if (r >= 0) m -= Q[(size_t)r * DH + tid];
        m = fmaxf(m, 0.f);
        if (Hout) Hout[(size_t)ee * DH + tid] = m;
        else atomicAdd(&MV[(size_t)s * DH + tid], m);
    }
}

// ---------------------------------------------------------------------------
extern "C" void kernel_launch(void* const* d_in, const int* in_sizes, int n_in,
                              void* d_out, int out_size)
{
    const float* V   = (const float*)d_in[0];
    const float* Ef  = (const float*)d_in[1];
    const void*  EI  = d_in[2];
    const void*  REV = d_in[3];
    const float* Wi  = (const float*)d_in[4];
    const float* bi  = (const float*)d_in[5];
    const float* Wh  = (const float*)d_in[6];
    const float* bh  = (const float*)d_in[7];
    const float* Wo  = (const float*)d_in[8];
    const float* bo  = (const float*)d_in[9];
    float* out = (float*)d_out;

    float *pVW, *pH0, *pH1, *pQ, *pNM, *pMV;
    cudaGetSymbolAddress((void**)&pVW, g_VW);
    cudaGetSymbolAddress((void**)&pH0, g_H0);
    cudaGetSymbolAddress((void**)&pH1, g_H1);
    cudaGetSymbolAddress((void**)&pQ,  g_Q);
    cudaGetSymbolAddress((void**)&pNM, g_NM);
    cudaGetSymbolAddress((void**)&pMV, g_MV);

    static int smem_set = 0;
    if (!smem_set) {
        cudaFuncSetAttribute(k_gemm, cudaFuncAttributeMaxDynamicSharedMemorySize,
                             SW_WORDS * 4);
        smem_set = 1;
    }

    const int GN = (NN + 127) / 128;   // 1563
    const int GE = (NE + 127) / 128;   // 3125
    const long long N4 = (long long)NN * DH / 4;
    const size_t SMB = SW_WORDS * 4;

    k_detect<<<1, 32>>>((const unsigned int*)EI);

    // weight prep (transposed, padded, split bf16)
    k_makeB<<<200, 256>>>(Wi, 0,   133, 192, BT_WV);
    k_makeB<<<200, 256>>>(Wi, 133, 14,  64,  BT_WE);
    k_makeB<<<200, 256>>>(Wh, 0,   200, 256, BT_WH);
    k_makeB<<<200, 256>>>(Wo, 0,   133, 192, BT_WOV);
    k_makeB<<<200, 256>>>(Wo, 133, 200, 256, BT_WOH);

    // P = V@Wv
    k_gemm<<<GN, 256, SMB>>>(V, NN, 133, 192, BT_WV, 0,
                             nullptr, nullptr, nullptr, 0, pVW, nullptr);
    // H0 = relu(E@We + P[src] + bi)
    k_gemm<<<GE, 256, SMB>>>(Ef, NE, 14, 64, BT_WE, 1,
                             bi, pVW, EI, 0LL, pH0, nullptr);

    // iter 1: Q = H0@Wh (+scatter NM via dst); H1 = relu(H0 + NM[src] - Q[rev] + bh)
    k_zero<<<4096, 256>>>((float4*)pNM, N4);
    k_gemm<<<GE, 256, SMB>>>(pH0, NE, 200, 256, BT_WH, 2,
                             nullptr, nullptr, EI, (long long)NE, pQ, pNM);
    k_combine<<<NE / 32, 200>>>(pQ, pH0, pNM, bh, EI, REV, pH1, nullptr);

    // iter 2: Q = H1@Wh (+scatter NM); H2 scattered into MV[src]
    k_zero<<<4096, 256>>>((float4*)pNM, N4);
    k_gemm<<<GE, 256, SMB>>>(pH1, NE, 200, 256, BT_WH, 2,
                             nullptr, nullptr, EI, (long long)NE, pQ, pNM);
    k_zero<<<4096, 256>>>((float4*)pMV, N4);
    k_combine<<<NE / 32, 200>>>(pQ, pH0, pNM, bh, EI, REV, nullptr, pMV);

    // readout: C1 = V@Wov; out = relu(MV@Woh + C1 + bo)
    k_gemm<<<GN, 256, SMB>>>(V, NN, 133, 192, BT_WOV, 0,
                             nullptr, nullptr, nullptr, 0, pVW, nullptr);
    k_gemm<<<GN, 256, SMB>>>(pMV, NN, 200, 256, BT_WOH, 3,
                             bo, pVW, nullptr, 0, out, nullptr);
}

// round 6
// speedup vs baseline: 1.0006x; 1.0006x over previous
#include <cuda_runtime.h>
#include <cuda_bf16.h>
#include <stdint.h>

#define NN 200000
#define NE 400000
#define DV 133
#define DE 14
#define DH 200

// ---------------------------------------------------------------------------
// Scratch
// ---------------------------------------------------------------------------
__device__ float g_VW[(size_t)NN * DH];
__device__ float g_H0[(size_t)NE * DH];
__device__ float g_H1[(size_t)NE * DH];
__device__ float g_Q [(size_t)NE * DH];
__device__ float g_NM[(size_t)NN * DH];
__device__ float g_MV[(size_t)NN * DH];
__device__ __nv_bfloat16 g_BThi[192000];
__device__ __nv_bfloat16 g_BTlo[192000];
__device__ int g_idx64;

#define BT_WV   0LL       /* K=133 Kpad=192 */
#define BT_WE   38400LL   /* K=14  Kpad=64  */
#define BT_WH   51200LL   /* K=200 Kpad=256 */
#define BT_WOV  102400LL  /* K=133 Kpad=192 */
#define BT_WOH  140800LL  /* K=200 Kpad=256 */

// ---------------------------------------------------------------------------
__global__ void k_detect(const unsigned int* __restrict__ ei) {
    if (threadIdx.x == 0 && blockIdx.x == 0) {
        int all0 = 1;
        for (int i = 1; i < 256; i += 2)
            if (ei[i] != 0u) { all0 = 0; break; }
        g_idx64 = all0;
    }
}
__device__ __forceinline__ int load_idx(const void* p, long long i, int is64) {
    if (is64) return (int)((const long long*)p)[i];
    return ((const int*)p)[i];
}

// Bt[n][k] = W[roff+k][n], split hi/lo bf16, K-padded with zeros
__global__ void k_makeB(const float* __restrict__ W, int roff, int K, int Kpad, long long off) {
    long long tot = 200LL * Kpad;
    for (long long i = (long long)blockIdx.x * blockDim.x + threadIdx.x; i < tot;
         i += (long long)gridDim.x * blockDim.x) {
        int n = (int)(i / Kpad), k = (int)(i % Kpad);
        float v = (k < K) ? W[(size_t)(roff + k) * DH + n] : 0.f;
        __nv_bfloat16 h = __float2bfloat16(v);
        g_BThi[off + i] = h;
        g_BTlo[off + i] = __float2bfloat16(v - __bfloat162float(h));
    }
}

__global__ void k_zero(float4* __restrict__ p, long long n4) {
    float4 z = make_float4(0.f, 0.f, 0.f, 0.f);
    for (long long i = (long long)blockIdx.x * blockDim.x + threadIdx.x; i < n4;
         i += (long long)gridDim.x * blockDim.x)
        p[i] = z;
}

// ---------------------------------------------------------------------------
// mma.sync m16n8k16 bf16 (base ISA, runs on tensor pipe)
// ---------------------------------------------------------------------------
__device__ __forceinline__ void mma16816(float* c, const uint32_t* a, const uint32_t* b) {
    asm volatile("mma.sync.aligned.m16n8k16.row.col.f32.bf16.bf16.f32 "
        "{%0,%1,%2,%3}, {%4,%5,%6,%7}, {%8,%9}, {%0,%1,%2,%3};"
        : "+f"(c[0]), "+f"(c[1]), "+f"(c[2]), "+f"(c[3])
        : "r"(a[0]), "r"(a[1]), "r"(a[2]), "r"(a[3]), "r"(b[0]), "r"(b[1]));
}

__device__ __forceinline__ void split2(float v0, float v1, uint32_t& hw, uint32_t& lw) {
    __nv_bfloat16 h0 = __float2bfloat16(v0);
    __nv_bfloat16 h1 = __float2bfloat16(v1);
    __nv_bfloat16 l0 = __float2bfloat16(v0 - __bfloat162float(h0));
    __nv_bfloat16 l1 = __float2bfloat16(v1 - __bfloat162float(h1));
    hw = (uint32_t)__bfloat16_as_ushort(h0) | ((uint32_t)__bfloat16_as_ushort(h1) << 16);
    lw = (uint32_t)__bfloat16_as_ushort(l0) | ((uint32_t)__bfloat16_as_ushort(l1) << 16);
}

#define PITCH 40               /* words per smem row: conflict-free LDS.64 */
#define SW_AH 0
#define SW_AL 5120             /* 128*40 */
#define SW_BH 10240
#define SW_BL 18240            /* +200*40 */
#define SW_WORDS 26240         /* *4 = 104960 bytes */

// ---------------------------------------------------------------------------
// C[Mrows,200] = A[Mrows,K] @ W[K,200]  (3-term split bf16 mma, fp32 acc)
// mode 0: C = acc
// mode 1: C = relu(acc + addend[idx[row]] + bias)
// mode 2: C = acc; scat[idx[row]] += acc (atomic)
// mode 3: C = relu(acc + addend[row] + bias)
// ---------------------------------------------------------------------------
__global__ __launch_bounds__(256, 1)
void k_gemm(const float* __restrict__ A, int Mrows, int K, int Kpad,
            long long bt_off, int mode,
            const float* __restrict__ bias,
            const float* __restrict__ addend,
            const void* __restrict__ idx, long long idx_off,
            float* __restrict__ C, float* __restrict__ scat)
{
    extern __shared__ uint32_t sw[];
    const int tid = threadIdx.x, wid = tid >> 5, lane = tid & 31;
    const int g = lane >> 2, tig = lane & 3;
    const int e0 = blockIdx.x * 128, m0 = wid * 16;
    const int KSTEPS = (K + 15) >> 4;
    const int CC = (KSTEPS + 3) >> 2;
    const int kpw = Kpad >> 1;
    const uint32_t* __restrict__ Bh = (const uint32_t*)g_BThi + (bt_off >> 1);
    const uint32_t* __restrict__ Bl = (const uint32_t*)g_BTlo + (bt_off >> 1);

    float acc[25][4];
#pragma unroll
    for (int nf = 0; nf < 25; nf++)
#pragma unroll
        for (int i = 0; i < 4; i++) acc[nf][i] = 0.f;

    for (int c = 0; c < CC; c++) {
        const int kb = c << 6;
        __syncthreads();
        // A tile: 128 rows x 32 words, permuted [0,4,1,5,2,6,3,7] per kstep
        for (int pos = tid; pos < 4096; pos += 256) {
            int row = pos >> 5, q = pos & 31;
            int ql = q & 7, s = q >> 3;
            int ow = (ql & 1) ? ((ql >> 1) + 4) : (ql >> 1);
            int k0 = kb + ((s << 3) + ow) * 2;
            int r = e0 + row;
            float v0 = 0.f, v1 = 0.f;
            if (r < Mrows) {
                const float* ap = A + (size_t)r * K;
                if (k0 < K) v0 = ap[k0];
                if (k0 + 1 < K) v1 = ap[k0 + 1];
            }
            uint32_t hw, lw;
            split2(v0, v1, hw, lw);
            sw[SW_AH + row * PITCH + q] = hw;
            sw[SW_AL + row * PITCH + q] = lw;
        }
        // B tile: 200 rows x 32 words (pre-split, just permute-copy)
        for (int pos = tid; pos < 6400; pos += 256) {
            int n = pos >> 5, q = pos & 31;
            int ql = q & 7, s = q >> 3;
            int ow = (ql & 1) ? ((ql >> 1) + 4) : (ql >> 1);
            int wi = n * kpw + (kb >> 1) + (s << 3) + ow;
            sw[SW_BH + n * PITCH + q] = Bh[wi];
            sw[SW_BL + n * PITCH + q] = Bl[wi];
        }
        __syncthreads();

        int ksl = KSTEPS - (c << 2);
        if (ksl > 4) ksl = 4;
        for (int s = 0; s < ksl; s++) {
            uint32_t ah[4], al[4];
            int aw = (m0 + g) * PITCH + (s << 3) + (tig << 1);
            {
                uint2 t0 = *(const uint2*)&sw[SW_AH + aw];
                uint2 t1 = *(const uint2*)&sw[SW_AH + aw + 8 * PITCH];
                ah[0] = t0.x; ah[2] = t0.y; ah[1] = t1.x; ah[3] = t1.y;
                uint2 u0 = *(const uint2*)&sw[SW_AL + aw];
                uint2 u1 = *(const uint2*)&sw[SW_AL + aw + 8 * PITCH];
                al[0] = u0.x; al[2] = u0.y; al[1] = u1.x; al[3] = u1.y;
            }
#pragma unroll
            for (int nf = 0; nf < 25; nf++) {
                int bw = (nf * 8 + g) * PITCH + (s << 3) + (tig << 1);
                uint2 bh2 = *(const uint2*)&sw[SW_BH + bw];
                uint2 bl2 = *(const uint2*)&sw[SW_BL + bw];
                uint32_t bh[2] = { bh2.x, bh2.y };
                uint32_t bl[2] = { bl2.x, bl2.y };
                mma16816(acc[nf], ah, bh);
                mma16816(acc[nf], al, bh);
                mma16816(acc[nf], ah, bl);
            }
        }
    }

    // ---- epilogue ----
    const int is64 = g_idx64;
    const int r1 = e0 + m0 + g, r2 = r1 + 8;
    const bool v1 = r1 < Mrows, v2 = r2 < Mrows;
    long long gi1 = 0, gi2 = 0;
    if (mode == 1 || mode == 2) {
        if (v1) gi1 = load_idx(idx, idx_off + r1, is64);
        if (v2) gi2 = load_idx(idx, idx_off + r2, is64);
    }
    const float* ar1 = (mode == 1) ? addend + (size_t)gi1 * DH
                     : (mode == 3) ? addend + (size_t)r1 * DH : nullptr;
    const float* ar2 = (mode == 1) ? addend + (size_t)gi2 * DH
                     : (mode == 3) ? addend + (size_t)r2 * DH : nullptr;

#pragma unroll
    for (int nf = 0; nf < 25; nf++) {
        int col = nf * 8 + tig * 2;
        if (v1) {
            float x0 = acc[nf][0], x1 = acc[nf][1];
            if (mode == 1 || mode == 3) {
                x0 = fmaxf(x0 + ar1[col] + bias[col], 0.f);
                x1 = fmaxf(x1 + ar1[col + 1] + bias[col + 1], 0.f);
            }
            *(float2*)&C[(size_t)r1 * DH + col] = make_float2(x0, x1);
            if (mode == 2) {
                atomicAdd(&scat[(size_t)gi1 * DH + col], x0);
                atomicAdd(&scat[(size_t)gi1 * DH + col + 1], x1);
            }
        }
        if (v2) {
            float x2 = acc[nf][2], x3 = acc[nf][3];
            if (mode == 1 || mode == 3) {
                x2 = fmaxf(x2 + ar2[col] + bias[col], 0.f);
                x3 = fmaxf(x3 + ar2[col + 1] + bias[col + 1], 0.f);
            }
            *(float2*)&C[(size_t)r2 * DH + col] = make_float2(x2, x3);
            if (mode == 2) {
                atomicAdd(&scat[(size_t)gi2 * DH + col], x2);
                atomicAdd(&scat[(size_t)gi2 * DH + col + 1], x3);
            }
        }
    }
}

// ---------------------------------------------------------------------------
// H = relu(H0 + NMQ[src] - Q[rev]*(rev!=e) + bh); store Hout or scatter MV[src]
// ---------------------------------------------------------------------------
__global__ __launch_bounds__(200) void k_combine(
    const float* __restrict__ Q, const float* __restrict__ H0b,
    const float* __restrict__ NMQ, const float* __restrict__ bh,
    const void* __restrict__ EI, const void* __restrict__ REV,
    float* __restrict__ Hout, float* __restrict__ MV)
{
    __shared__ int s_src[32], s_rev[32];
    const int tid = threadIdx.x;
    const long long e0 = (long long)blockIdx.x * 32;
    const int is64 = g_idx64;
    if (tid < 32) {
        s_src[tid] = load_idx(EI, e0 + tid, is64);
        long long r = (long long)load_idx(REV, e0 + tid, is64);
        s_rev[tid] = (r == e0 + tid) ? -1 : (int)r;
    }
    __syncthreads();
    const float b = bh[tid];
#pragma unroll 4
    for (int e = 0; e < 32; e++) {
        long long ee = e0 + e;
        int s = s_src[e], r = s_rev[e];
        float m = H0b[(size_t)ee * DH + tid] + NMQ[(size_t)s * DH + tid] + b;
        if (r >= 0) m -= Q[(size_t)r * DH + tid];
        m = fmaxf(m, 0.f);
        if (Hout) Hout[(size_t)ee * DH + tid] = m;
        else atomicAdd(&MV[(size_t)s * DH + tid], m);
    }
}

// ---------------------------------------------------------------------------
extern "C" void kernel_launch(void* const* d_in, const int* in_sizes, int n_in,
                              void* d_out, int out_size)
{
    const float* V   = (const float*)d_in[0];
    const float* Ef  = (const float*)d_in[1];
    const void*  EI  = d_in[2];
    const void*  REV = d_in[3];
    const float* Wi  = (const float*)d_in[4];
    const float* bi  = (const float*)d_in[5];
    const float* Wh  = (const float*)d_in[6];
    const float* bh  = (const float*)d_in[7];
    const float* Wo  = (const float*)d_in[8];
    const float* bo  = (const float*)d_in[9];
    float* out = (float*)d_out;

    float *pVW, *pH0, *pH1, *pQ, *pNM, *pMV;
    cudaGetSymbolAddress((void**)&pVW, g_VW);
    cudaGetSymbolAddress((void**)&pH0, g_H0);
    cudaGetSymbolAddress((void**)&pH1, g_H1);
    cudaGetSymbolAddress((void**)&pQ,  g_Q);
    cudaGetSymbolAddress((void**)&pNM, g_NM);
    cudaGetSymbolAddress((void**)&pMV, g_MV);

    static int smem_set = 0;
    if (!smem_set) {
        cudaFuncSetAttribute(k_gemm, cudaFuncAttributeMaxDynamicSharedMemorySize,
                             SW_WORDS * 4);
        smem_set = 1;
    }

    const int GN = (NN + 127) / 128;   // 1563
    const int GE = (NE + 127) / 128;   // 3125
    const long long N4 = (long long)NN * DH / 4;
    const size_t SMB = SW_WORDS * 4;

    k_detect<<<1, 32>>>((const unsigned int*)EI);

    // weight prep (transposed, padded, split bf16)
    k_makeB<<<200, 256>>>(Wi, 0,   133, 192, BT_WV);
    k_makeB<<<200, 256>>>(Wi, 133, 14,  64,  BT_WE);
    k_makeB<<<200, 256>>>(Wh, 0,   200, 256, BT_WH);
    k_makeB<<<200, 256>>>(Wo, 0,   133, 192, BT_WOV);
    k_makeB<<<200, 256>>>(Wo, 133, 200, 256, BT_WOH);

    // P = V@Wv
    k_gemm<<<GN, 256, SMB>>>(V, NN, 133, 192, BT_WV, 0,
                             nullptr, nullptr, nullptr, 0, pVW, nullptr);
    // H0 = relu(E@We + P[src] + bi)
    k_gemm<<<GE, 256, SMB>>>(Ef, NE, 14, 64, BT_WE, 1,
                             bi, pVW, EI, 0LL, pH0, nullptr);

    // iter 1: Q = H0@Wh (+scatter NM via dst); H1 = relu(H0 + NM[src] - Q[rev] + bh)
    k_zero<<<4096, 256>>>((float4*)pNM, N4);
    k_gemm<<<GE, 256, SMB>>>(pH0, NE, 200, 256, BT_WH, 2,
                             nullptr, nullptr, EI, (long long)NE, pQ, pNM);
    k_combine<<<NE / 32, 200>>>(pQ, pH0, pNM, bh, EI, REV, pH1, nullptr);

    // iter 2: Q = H1@Wh (+scatter NM); H2 scattered into MV[src]
    k_zero<<<4096, 256>>>((float4*)pNM, N4);
    k_gemm<<<GE, 256, SMB>>>(pH1, NE, 200, 256, BT_WH, 2,
                             nullptr, nullptr, EI, (long long)NE, pQ, pNM);
    k_zero<<<4096, 256>>>((float4*)pMV, N4);
    k_combine<<<NE / 32, 200>>>(pQ, pH0, pNM, bh, EI, REV, nullptr, pMV);

    // readout: C1 = V@Wov; out = relu(MV@Woh + C1 + bo)
    k_gemm<<<GN, 256, SMB>>>(V, NN, 133, 192, BT_WOV, 0,
                             nullptr, nullptr, nullptr, 0, pVW, nullptr);
    k_gemm<<<GN, 256, SMB>>>(pMV, NN, 200, 256, BT_WOH, 3,
                             bo, pVW, nullptr, 0, out, nullptr);
}

// round 7
// speedup vs baseline: 1.0184x; 1.0178x over previous
#include <cuda_runtime.h>
#include <cuda_bf16.h>
#include <stdint.h>

#define NN 200000
#define NE 400000
#define DV 133
#define DE 14
#define DH 200

// ---------------------------------------------------------------------------
// Scratch
// ---------------------------------------------------------------------------
__device__ float g_VW[(size_t)NN * DH];
__device__ float g_H0[(size_t)NE * DH];
__device__ float g_H1[(size_t)NE * DH];
__device__ float g_Q [(size_t)NE * DH];
__device__ float g_NM[(size_t)NN * DH];
__device__ float g_MV[(size_t)NN * DH];
__device__ __nv_bfloat16 g_BThi[192000];
__device__ __nv_bfloat16 g_BTlo[192000];
__device__ int g_idx64;

#define BT_WV   0LL       /* K=133 Kpad=192 */
#define BT_WE   38400LL   /* K=14  Kpad=64  */
#define BT_WH   51200LL   /* K=200 Kpad=256 */
#define BT_WOV  102400LL  /* K=133 Kpad=192 */
#define BT_WOH  140800LL  /* K=200 Kpad=256 */

// ---------------------------------------------------------------------------
__global__ void k_detect(const unsigned int* __restrict__ ei) {
    if (threadIdx.x == 0 && blockIdx.x == 0) {
        int all0 = 1;
        for (int i = 1; i < 256; i += 2)
            if (ei[i] != 0u) { all0 = 0; break; }
        g_idx64 = all0;
    }
}
__device__ __forceinline__ int load_idx(const void* p, long long i, int is64) {
    if (is64) return (int)((const long long*)p)[i];
    return ((const int*)p)[i];
}

// Bt[n][k] = W[roff+k][n], split hi/lo bf16, K-padded with zeros
__global__ void k_makeB(const float* __restrict__ W, int roff, int K, int Kpad, long long off) {
    long long tot = 200LL * Kpad;
    for (long long i = (long long)blockIdx.x * blockDim.x + threadIdx.x; i < tot;
         i += (long long)gridDim.x * blockDim.x) {
        int n = (int)(i / Kpad), k = (int)(i % Kpad);
        float v = (k < K) ? W[(size_t)(roff + k) * DH + n] : 0.f;
        __nv_bfloat16 h = __float2bfloat16(v);
        g_BThi[off + i] = h;
        g_BTlo[off + i] = __float2bfloat16(v - __bfloat162float(h));
    }
}

__global__ void k_zero(float4* __restrict__ p, long long n4) {
    float4 z = make_float4(0.f, 0.f, 0.f, 0.f);
    for (long long i = (long long)blockIdx.x * blockDim.x + threadIdx.x; i < n4;
         i += (long long)gridDim.x * blockDim.x)
        p[i] = z;
}

// ---------------------------------------------------------------------------
// mma.sync m16n8k16 bf16 (base ISA, runs on tensor pipe)
// ---------------------------------------------------------------------------
__device__ __forceinline__ void mma16816(float* c, const uint32_t* a, const uint32_t* b) {
    asm volatile("mma.sync.aligned.m16n8k16.row.col.f32.bf16.bf16.f32 "
        "{%0,%1,%2,%3}, {%4,%5,%6,%7}, {%8,%9}, {%0,%1,%2,%3};"
        : "+f"(c[0]), "+f"(c[1]), "+f"(c[2]), "+f"(c[3])
        : "r"(a[0]), "r"(a[1]), "r"(a[2]), "r"(a[3]), "r"(b[0]), "r"(b[1]));
}

__device__ __forceinline__ void split2(float v0, float v1, uint32_t& hw, uint32_t& lw) {
    __nv_bfloat16 h0 = __float2bfloat16(v0);
    __nv_bfloat16 h1 = __float2bfloat16(v1);
    __nv_bfloat16 l0 = __float2bfloat16(v0 - __bfloat162float(h0));
    __nv_bfloat16 l1 = __float2bfloat16(v1 - __bfloat162float(h1));
    hw = (uint32_t)__bfloat16_as_ushort(h0) | ((uint32_t)__bfloat16_as_ushort(h1) << 16);
    lw = (uint32_t)__bfloat16_as_ushort(l0) | ((uint32_t)__bfloat16_as_ushort(l1) << 16);
}

#define PITCH 40               /* words per smem row: conflict-free LDS.64 */
#define SW_AH 0
#define SW_AL 5120             /* 128*40 */
#define SW_BH 10240
#define SW_BL 18240            /* +200*40 */
#define SW_WORDS 26240         /* *4 = 104960 bytes */

// ---------------------------------------------------------------------------
// C[Mrows,200] = A[Mrows,K] @ W[K,200]  (3-term split bf16 mma, fp32 acc)
// mode 0: C = acc
// mode 1: C = relu(acc + addend[idx[row]] + bias)
// mode 2: C = acc; scat[idx[row]] += acc (atomic)
// mode 3: C = relu(acc + addend[row] + bias)
// ---------------------------------------------------------------------------
__global__ __launch_bounds__(256, 1)
void k_gemm(const float* __restrict__ A, int Mrows, int K, int Kpad,
            long long bt_off, int mode,
            const float* __restrict__ bias,
            const float* __restrict__ addend,
            const void* __restrict__ idx, long long idx_off,
            float* __restrict__ C, float* __restrict__ scat)
{
    extern __shared__ uint32_t sw[];
    const int tid = threadIdx.x, wid = tid >> 5, lane = tid & 31;
    const int g = lane >> 2, tig = lane & 3;
    const int e0 = blockIdx.x * 128, m0 = wid * 16;
    const int KSTEPS = (K + 15) >> 4;
    const int CC = (KSTEPS + 3) >> 2;
    const int kpw = Kpad >> 1;
    const uint32_t* __restrict__ Bh = (const uint32_t*)g_BThi + (bt_off >> 1);
    const uint32_t* __restrict__ Bl = (const uint32_t*)g_BTlo + (bt_off >> 1);

    float acc[25][4];
#pragma unroll
    for (int nf = 0; nf < 25; nf++)
#pragma unroll
        for (int i = 0; i < 4; i++) acc[nf][i] = 0.f;

    for (int c = 0; c < CC; c++) {
        const int kb = c << 6;
        __syncthreads();
        // A tile: 128 rows x 32 words, permuted [0,4,1,5,2,6,3,7] per kstep
        for (int pos = tid; pos < 4096; pos += 256) {
            int row = pos >> 5, q = pos & 31;
            int ql = q & 7, s = q >> 3;
            int ow = (ql & 1) ? ((ql >> 1) + 4) : (ql >> 1);
            int k0 = kb + ((s << 3) + ow) * 2;
            int r = e0 + row;
            float v0 = 0.f, v1 = 0.f;
            if (r < Mrows) {
                const float* ap = A + (size_t)r * K;
                if (k0 < K) v0 = ap[k0];
                if (k0 + 1 < K) v1 = ap[k0 + 1];
            }
            uint32_t hw, lw;
            split2(v0, v1, hw, lw);
            sw[SW_AH + row * PITCH + q] = hw;
            sw[SW_AL + row * PITCH + q] = lw;
        }
        // B tile: 200 rows x 32 words (pre-split, just permute-copy)
        for (int pos = tid; pos < 6400; pos += 256) {
            int n = pos >> 5, q = pos & 31;
            int ql = q & 7, s = q >> 3;
            int ow = (ql & 1) ? ((ql >> 1) + 4) : (ql >> 1);
            int wi = n * kpw + (kb >> 1) + (s << 3) + ow;
            sw[SW_BH + n * PITCH + q] = Bh[wi];
            sw[SW_BL + n * PITCH + q] = Bl[wi];
        }
        __syncthreads();

        int ksl = KSTEPS - (c << 2);
        if (ksl > 4) ksl = 4;
        for (int s = 0; s < ksl; s++) {
            uint32_t ah[4], al[4];
            int aw = (m0 + g) * PITCH + (s << 3) + (tig << 1);
            {
                uint2 t0 = *(const uint2*)&sw[SW_AH + aw];
                uint2 t1 = *(const uint2*)&sw[SW_AH + aw + 8 * PITCH];
                ah[0] = t0.x; ah[2] = t0.y; ah[1] = t1.x; ah[3] = t1.y;
                uint2 u0 = *(const uint2*)&sw[SW_AL + aw];
                uint2 u1 = *(const uint2*)&sw[SW_AL + aw + 8 * PITCH];
                al[0] = u0.x; al[2] = u0.y; al[1] = u1.x; al[3] = u1.y;
            }
#pragma unroll
            for (int nf = 0; nf < 25; nf++) {
                int bw = (nf * 8 + g) * PITCH + (s << 3) + (tig << 1);
                uint2 bh2 = *(const uint2*)&sw[SW_BH + bw];
                uint2 bl2 = *(const uint2*)&sw[SW_BL + bw];
                uint32_t bh[2] = { bh2.x, bh2.y };
                uint32_t bl[2] = { bl2.x, bl2.y };
                mma16816(acc[nf], ah, bh);
                mma16816(acc[nf], al, bh);
                mma16816(acc[nf], ah, bl);
            }
        }
    }

    // ---- epilogue ----
    const int is64 = g_idx64;
    const int r1 = e0 + m0 + g, r2 = r1 + 8;
    const bool v1 = r1 < Mrows, v2 = r2 < Mrows;
    long long gi1 = 0, gi2 = 0;
    if (mode == 1 || mode == 2) {
        if (v1) gi1 = load_idx(idx, idx_off + r1, is64);
        if (v2) gi2 = load_idx(idx, idx_off + r2, is64);
    }
    const float* ar1 = (mode == 1) ? addend + (size_t)gi1 * DH
                     : (mode == 3) ? addend + (size_t)r1 * DH : nullptr;
    const float* ar2 = (mode == 1) ? addend + (size_t)gi2 * DH
                     : (mode == 3) ? addend + (size_t)r2 * DH : nullptr;

#pragma unroll
    for (int nf = 0; nf < 25; nf++) {
        int col = nf * 8 + tig * 2;
        if (v1) {
            float x0 = acc[nf][0], x1 = acc[nf][1];
            if (mode == 1 || mode == 3) {
                x0 = fmaxf(x0 + ar1[col] + bias[col], 0.f);
                x1 = fmaxf(x1 + ar1[col + 1] + bias[col + 1], 0.f);
            }
            *(float2*)&C[(size_t)r1 * DH + col] = make_float2(x0, x1);
            if (mode == 2) {
                atomicAdd(&scat[(size_t)gi1 * DH + col], x0);
                atomicAdd(&scat[(size_t)gi1 * DH + col + 1], x1);
            }
        }
        if (v2) {
            float x2 = acc[nf][2], x3 = acc[nf][3];
            if (mode == 1 || mode == 3) {
                x2 = fmaxf(x2 + ar2[col] + bias[col], 0.f);
                x3 = fmaxf(x3 + ar2[col + 1] + bias[col + 1], 0.f);
            }
            *(float2*)&C[(size_t)r2 * DH + col] = make_float2(x2, x3);
            if (mode == 2) {
                atomicAdd(&scat[(size_t)gi2 * DH + col], x2);
                atomicAdd(&scat[(size_t)gi2 * DH + col + 1], x3);
            }
        }
    }
}

// ---------------------------------------------------------------------------
// H = relu(H0 + NMQ[src] - Q[rev]*(rev!=e) + bh); store Hout or scatter MV[src]
// ---------------------------------------------------------------------------
__global__ __launch_bounds__(200) void k_combine(
    const float* __restrict__ Q, const float* __restrict__ H0b,
    const float* __restrict__ NMQ, const float* __restrict__ bh,
    const void* __restrict__ EI, const void* __restrict__ REV,
    float* __restrict__ Hout, float* __restrict__ MV)
{
    __shared__ int s_src[32], s_rev[32];
    const int tid = threadIdx.x;
    const long long e0 = (long long)blockIdx.x * 32;
    const int is64 = g_idx64;
    if (tid < 32) {
        s_src[tid] = load_idx(EI, e0 + tid, is64);
        long long r = (long long)load_idx(REV, e0 + tid, is64);
        s_rev[tid] = (r == e0 + tid) ? -1 : (int)r;
    }
    __syncthreads();
    const float b = bh[tid];
#pragma unroll 4
    for (int e = 0; e < 32; e++) {
        long long ee = e0 + e;
        int s = s_src[e], r = s_rev[e];
        float m = H0b[(size_t)ee * DH + tid] + NMQ[(size_t)s * DH + tid] + b;
        if (r >= 0) m -= Q[(size_t)r * DH + tid];
        m = fmaxf(m, 0.f);
        if (Hout) Hout[(size_t)ee * DH + tid] = m;
        else atomicAdd(&MV[(size_t)s * DH + tid], m);
    }
}

// ---------------------------------------------------------------------------
extern "C" void kernel_launch(void* const* d_in, const int* in_sizes, int n_in,
                              void* d_out, int out_size)
{
    const float* V   = (const float*)d_in[0];
    const float* Ef  = (const float*)d_in[1];
    const void*  EI  = d_in[2];
    const void*  REV = d_in[3];
    const float* Wi  = (const float*)d_in[4];
    const float* bi  = (const float*)d_in[5];
    const float* Wh  = (const float*)d_in[6];
    const float* bh  = (const float*)d_in[7];
    const float* Wo  = (const float*)d_in[8];
    const float* bo  = (const float*)d_in[9];
    float* out = (float*)d_out;

    float *pVW, *pH0, *pH1, *pQ, *pNM, *pMV;
    cudaGetSymbolAddress((void**)&pVW, g_VW);
    cudaGetSymbolAddress((void**)&pH0, g_H0);
    cudaGetSymbolAddress((void**)&pH1, g_H1);
    cudaGetSymbolAddress((void**)&pQ,  g_Q);
    cudaGetSymbolAddress((void**)&pNM, g_NM);
    cudaGetSymbolAddress((void**)&pMV, g_MV);

    static int smem_set = 0;
    if (!smem_set) {
        cudaFuncSetAttribute(k_gemm, cudaFuncAttributeMaxDynamicSharedMemorySize,
                             SW_WORDS * 4);
        smem_set = 1;
    }

    const int GN = (NN + 127) / 128;   // 1563
    const int GE = (NE + 127) / 128;   // 3125
    const long long N4 = (long long)NN * DH / 4;
    const size_t SMB = SW_WORDS * 4;

    k_detect<<<1, 32>>>((const unsigned int*)EI);

    // weight prep (transposed, padded, split bf16)
    k_makeB<<<200, 256>>>(Wi, 0,   133, 192, BT_WV);
    k_makeB<<<200, 256>>>(Wi, 133, 14,  64,  BT_WE);
    k_makeB<<<200, 256>>>(Wh, 0,   200, 256, BT_WH);
    k_makeB<<<200, 256>>>(Wo, 0,   133, 192, BT_WOV);
    k_makeB<<<200, 256>>>(Wo, 133, 200, 256, BT_WOH);

    // P = V@Wv
    k_gemm<<<GN, 256, SMB>>>(V, NN, 133, 192, BT_WV, 0,
                             nullptr, nullptr, nullptr, 0, pVW, nullptr);
    // H0 = relu(E@We + P[src] + bi)
    k_gemm<<<GE, 256, SMB>>>(Ef, NE, 14, 64, BT_WE, 1,
                             bi, pVW, EI, 0LL, pH0, nullptr);

    // iter 1: Q = H0@Wh (+scatter NM via dst); H1 = relu(H0 + NM[src] - Q[rev] + bh)
    k_zero<<<4096, 256>>>((float4*)pNM, N4);
    k_gemm<<<GE, 256, SMB>>>(pH0, NE, 200, 256, BT_WH, 2,
                             nullptr, nullptr, EI, (long long)NE, pQ, pNM);
    k_combine<<<NE / 32, 200>>>(pQ, pH0, pNM, bh, EI, REV, pH1, nullptr);

    // iter 2: Q = H1@Wh (+scatter NM); H2 scattered into MV[src]
    k_zero<<<4096, 256>>>((float4*)pNM, N4);
    k_gemm<<<GE, 256, SMB>>>(pH1, NE, 200, 256, BT_WH, 2,
                             nullptr, nullptr, EI, (long long)NE, pQ, pNM);
    k_zero<<<4096, 256>>>((float4*)pMV, N4);
    k_combine<<<NE / 32, 200>>>(pQ, pH0, pNM, bh, EI, REV, nullptr, pMV);

    // readout: C1 = V@Wov; out = relu(MV@Woh + C1 + bo)
    k_gemm<<<GN, 256, SMB>>>(V, NN, 133, 192, BT_WOV, 0,
                             nullptr, nullptr, nullptr, 0, pVW, nullptr);
    k_gemm<<<GN, 256, SMB>>>(pMV, NN, 200, 256, BT_WOH, 3,
                             bo, pVW, nullptr, 0, out, nullptr);
}